// round 4
// baseline (speedup 1.0000x reference)
#include <cuda_runtime.h>
#include <cuda_bf16.h>
#include <cstdint>

#define TTOK 4096
#define HD   1024
#define EN   8
#define ID   4096
#define RTOT 8192

typedef __nv_bfloat16 bf16;

// ----------------- scratch (device globals; no allocation allowed) -----------------
__device__ __align__(16) bf16  g_x_hi[(size_t)TTOK * HD];
__device__ __align__(16) bf16  g_x_lo[(size_t)TTOK * HD];
__device__ __align__(16) bf16  g_wg_hi[(size_t)EN * ID * HD];
__device__ __align__(16) bf16  g_wg_lo[(size_t)EN * ID * HD];
__device__ __align__(16) bf16  g_wu_hi[(size_t)EN * ID * HD];
__device__ __align__(16) bf16  g_wu_lo[(size_t)EN * ID * HD];
__device__ __align__(16) bf16  g_wd_hi[(size_t)EN * HD * ID];
__device__ __align__(16) bf16  g_wd_lo[(size_t)EN * HD * ID];
__device__ __align__(16) bf16  g_hid_hi[(size_t)RTOT * ID];
__device__ __align__(16) bf16  g_hid_lo[(size_t)RTOT * ID];
__device__ __align__(16) float g_contrib[(size_t)RTOT * HD];
__device__ int   g_counts[EN];
__device__ int   g_cursor[EN];
__device__ int   g_offsets[EN + 1];
__device__ float g_top_w[TTOK * 2];
__device__ int   g_top_e[TTOK * 2];
__device__ int   g_token_list[RTOT];
__device__ int   g_pair_row[TTOK * 2];

// ----------------- helpers -----------------
__device__ __forceinline__ void cp16(uint32_t dst, const void* src, bool pred) {
    int sz = pred ? 16 : 0;
    asm volatile("cp.async.cg.shared.global [%0], [%1], 16, %2;\n" :: "r"(dst), "l"(src), "r"(sz));
}
__device__ __forceinline__ void ldsm4(uint32_t* r, uint32_t a) {
    asm volatile("ldmatrix.sync.aligned.m8n8.x4.shared.b16 {%0,%1,%2,%3}, [%4];\n"
                 : "=r"(r[0]), "=r"(r[1]), "=r"(r[2]), "=r"(r[3]) : "r"(a));
}
__device__ __forceinline__ void mma16816(float* d, const uint32_t* a, const uint32_t* b) {
    asm volatile("mma.sync.aligned.m16n8k16.row.col.f32.bf16.bf16.f32 "
                 "{%0,%1,%2,%3}, {%4,%5,%6,%7}, {%8,%9}, {%0,%1,%2,%3};\n"
                 : "+f"(d[0]), "+f"(d[1]), "+f"(d[2]), "+f"(d[3])
                 : "r"(a[0]), "r"(a[1]), "r"(a[2]), "r"(a[3]), "r"(b[0]), "r"(b[1]));
}
__device__ __forceinline__ __nv_bfloat162 pk2(bf16 a, bf16 b) { __nv_bfloat162 t; t.x=a; t.y=b; return t; }

// ----------------- small kernels -----------------
__global__ void init_kernel() {
    int i = threadIdx.x;
    if (i < EN) { g_counts[i] = 0; g_cursor[i] = 0; }
}

__global__ void split_kernel(const float* __restrict__ src, bf16* __restrict__ hi,
                             bf16* __restrict__ lo, int n4) {
    int i = blockIdx.x * 256 + threadIdx.x;
    if (i >= n4) return;
    float4 v = reinterpret_cast<const float4*>(src)[i];
    bf16 h0 = __float2bfloat16(v.x), h1 = __float2bfloat16(v.y);
    bf16 h2 = __float2bfloat16(v.z), h3 = __float2bfloat16(v.w);
    reinterpret_cast<__nv_bfloat162*>(hi)[2*i]   = pk2(h0, h1);
    reinterpret_cast<__nv_bfloat162*>(hi)[2*i+1] = pk2(h2, h3);
    reinterpret_cast<__nv_bfloat162*>(lo)[2*i]   = pk2(__float2bfloat16(v.x - __bfloat162float(h0)),
                                                      __float2bfloat16(v.y - __bfloat162float(h1)));
    reinterpret_cast<__nv_bfloat162*>(lo)[2*i+1] = pk2(__float2bfloat16(v.z - __bfloat162float(h2)),
                                                      __float2bfloat16(v.w - __bfloat162float(h3)));
}

__global__ void router_kernel(const float* __restrict__ x, const float* __restrict__ gw) {
    int t = blockIdx.x;
    int lane = threadIdx.x & 31, w = threadIdx.x >> 5;       // warp w -> expert w
    __shared__ float lg[EN];
    const float* xr = x + (size_t)t * HD;
    const float* g  = gw + (size_t)w * HD;
    float s = 0.f;
    #pragma unroll 8
    for (int j = lane; j < HD; j += 32) s += xr[j] * g[j];
    #pragma unroll
    for (int o = 16; o; o >>= 1) s += __shfl_xor_sync(0xffffffffu, s, o);
    if (lane == 0) lg[w] = s;
    __syncthreads();
    if (threadIdx.x == 0) {
        float v0 = -1e30f; int e0 = 0;
        #pragma unroll
        for (int e = 0; e < EN; e++) if (lg[e] > v0) { v0 = lg[e]; e0 = e; }
        float v1 = -1e30f; int e1 = 0;
        #pragma unroll
        for (int e = 0; e < EN; e++) if (e != e0 && lg[e] > v1) { v1 = lg[e]; e1 = e; }
        float b = __expf(v1 - v0);
        g_top_e[2*t] = e0;  g_top_e[2*t+1] = e1;
        g_top_w[2*t] = 1.f / (1.f + b);  g_top_w[2*t+1] = b / (1.f + b);
        atomicAdd(&g_counts[e0], 1);
        atomicAdd(&g_counts[e1], 1);
    }
}

__global__ void scan_kernel() {
    if (threadIdx.x == 0) {
        int o = 0;
        for (int e = 0; e < EN; e++) { g_offsets[e] = o; o += g_counts[e]; }
        g_offsets[EN] = o;
    }
}

__global__ void scatter_kernel() {
    int t = blockIdx.x * 256 + threadIdx.x;
    if (t >= TTOK) return;
    #pragma unroll
    for (int k = 0; k < 2; k++) {
        int e = g_top_e[2*t+k];
        int r = g_offsets[e] + atomicAdd(&g_cursor[e], 1);
        g_token_list[r] = t;
        g_pair_row[2*t+k] = r;
    }
}

// ===================== GEMM1 fused: gate+up + SwiGLU -> split-bf16 hidden =====================
// Tile 128(M) x 64(N of I), BK=64, 3 stages.
// Stage layout (64 KB): Ah 16K | Al 16K | BgH 8K | BgL 8K | BuH 8K | BuL 8K.
__global__ __launch_bounds__(256) void gemm1_kernel() {
    const int e = blockIdx.z, mt = blockIdx.y, nt = blockIdx.x;
    const int count = g_counts[e];
    if (mt * 128 >= count) return;
    const int off = g_offsets[e];
    const int tid = threadIdx.x, lane = tid & 31, wid = tid >> 5;
    const int wm = wid & 3, wn = wid >> 2;                   // 4x2 warps -> 32x32 each
    extern __shared__ char smem[];
    __shared__ int rows_s[128];
    if (tid < 128) {
        int i = mt * 128 + tid;
        rows_s[tid] = (i < count) ? g_token_list[off + i] : -1;
    }
    __syncthreads();
    uint32_t sb0 = (uint32_t)__cvta_generic_to_shared(smem);
    const size_t wOff = ((size_t)e * ID + (size_t)nt * 64) * HD;
    const bf16* BgH = g_wg_hi + wOff;
    const bf16* BgL = g_wg_lo + wOff;
    const bf16* BuH = g_wu_hi + wOff;
    const bf16* BuL = g_wu_lo + wOff;

    float ag[2][4][4], au[2][4][4];
    #pragma unroll
    for (int a = 0; a < 2; a++)
        #pragma unroll
        for (int b = 0; b < 4; b++)
            #pragma unroll
            for (int c = 0; c < 4; c++) { ag[a][b][c] = 0.f; au[a][b][c] = 0.f; }

    auto load_stage = [&](int s, int kb) {
        uint32_t sb = sb0 + (uint32_t)s * 65536u;
        int k0 = kb * 64;
        #pragma unroll
        for (int it = 0; it < 4; ++it) {                     // A: 128 rows x 8 x 16B
            int ch = tid + it * 256, r = ch >> 3, c = ch & 7;
            int row = rows_s[r]; bool v = row >= 0;
            size_t o = (size_t)(v ? row : 0) * HD + (size_t)(k0 + c * 8);
            uint32_t d = sb + r * 128 + ((c ^ (r & 7)) << 4);
            cp16(d,          g_x_hi + o, v);
            cp16(d + 16384u, g_x_lo + o, v);
        }
        #pragma unroll
        for (int it = 0; it < 2; ++it) {                     // B: 64 rows x 8 x 16B (x4 mats)
            int ch = tid + it * 256, r = ch >> 3, c = ch & 7;
            size_t o = (size_t)r * HD + (size_t)(k0 + c * 8);
            uint32_t d = sb + 32768u + r * 128 + ((c ^ (r & 7)) << 4);
            cp16(d,          BgH + o, true);
            cp16(d + 8192u,  BgL + o, true);
            cp16(d + 16384u, BuH + o, true);
            cp16(d + 24576u, BuL + o, true);
        }
    };

    load_stage(0, 0);
    asm volatile("cp.async.commit_group;\n");
    load_stage(1, 1);
    asm volatile("cp.async.commit_group;\n");

    const int NK = HD / 64;   // 16
    for (int kb = 0; kb < NK; ++kb) {
        if (kb + 1 < NK) asm volatile("cp.async.wait_group 1;\n");
        else             asm volatile("cp.async.wait_group 0;\n");
        __syncthreads();
        int cur = kb % 3;
        uint32_t sb = sb0 + (uint32_t)cur * 65536u;
        #pragma unroll
        for (int q = 0; q < 4; ++q) {
            uint32_t aH[2][4], aL[2][4], gH[2][4], gL[2][4], uH[2][4], uL[2][4];
            int lr = lane & 15, lc = lane >> 4;
            #pragma unroll
            for (int mi = 0; mi < 2; ++mi) {
                int r = wm * 32 + mi * 16 + lr, c = 2 * q + lc;
                uint32_t ad = sb + r * 128 + ((c ^ (r & 7)) << 4);
                ldsm4(aH[mi], ad);
                ldsm4(aL[mi], ad + 16384u);
            }
            int bn = (lane & 7) + ((lane & 16) >> 1), bc = (lane >> 3) & 1;
            #pragma unroll
            for (int gi = 0; gi < 2; ++gi) {
                int r = wn * 32 + gi * 16 + bn, c = 2 * q + bc;
                uint32_t bd = sb + 32768u + r * 128 + ((c ^ (r & 7)) << 4);
                ldsm4(gH[gi], bd);
                ldsm4(gL[gi], bd + 8192u);
                ldsm4(uH[gi], bd + 16384u);
                ldsm4(uL[gi], bd + 24576u);
            }
            #pragma unroll
            for (int mi = 0; mi < 2; ++mi)
                #pragma unroll
                for (int nj = 0; nj < 4; ++nj) {
                    int gi = nj >> 1, sub = (nj & 1) * 2;
                    mma16816(ag[mi][nj], aH[mi], &gH[gi][sub]);
                    mma16816(ag[mi][nj], aH[mi], &gL[gi][sub]);
                    mma16816(ag[mi][nj], aL[mi], &gH[gi][sub]);
                    mma16816(au[mi][nj], aH[mi], &uH[gi][sub]);
                    mma16816(au[mi][nj], aH[mi], &uL[gi][sub]);
                    mma16816(au[mi][nj], aL[mi], &uH[gi][sub]);
                }
        }
        if (kb + 2 < NK) {
            load_stage((kb + 2) % 3, kb + 2);
            asm volatile("cp.async.commit_group;\n");
        }
    }

    // SwiGLU epilogue -> split-bf16 hidden
    int rl = lane >> 2, cl = (lane & 3) * 2;
    #pragma unroll
    for (int mi = 0; mi < 2; ++mi)
        #pragma unroll
        for (int nj = 0; nj < 4; ++nj)
            #pragma unroll
            for (int hh = 0; hh < 2; ++hh) {
                int i = mt * 128 + wm * 32 + mi * 16 + hh * 8 + rl;
                if (i < count) {
                    int col = nt * 64 + wn * 32 + nj * 8 + cl;
                    float g0 = ag[mi][nj][hh*2], g1 = ag[mi][nj][hh*2+1];
                    float u0 = au[mi][nj][hh*2], u1 = au[mi][nj][hh*2+1];
                    float h0 = g0 * (1.f / (1.f + __expf(-g0))) * u0;
                    float h1 = g1 * (1.f / (1.f + __expf(-g1))) * u1;
                    size_t idx = (size_t)(off + i) * ID + col;
                    bf16 a0 = __float2bfloat16(h0), a1 = __float2bfloat16(h1);
                    *reinterpret_cast<__nv_bfloat162*>(g_hid_hi + idx) = pk2(a0, a1);
                    *reinterpret_cast<__nv_bfloat162*>(g_hid_lo + idx) =
                        pk2(__float2bfloat16(h0 - __bfloat162float(a0)),
                            __float2bfloat16(h1 - __bfloat162float(a1)));
                }
            }
}

// ===================== GEMM2: down proj -> contrib =====================
// Tile 128(M) x 64(N of H), BK=64 over I, 3 stages. Stage (48 KB): Ah 16K | Al 16K | Bh 8K | Bl 8K.
__global__ __launch_bounds__(256) void gemm2_kernel() {
    const int e = blockIdx.z, mt = blockIdx.y, nt = blockIdx.x;
    const int count = g_counts[e];
    if (mt * 128 >= count) return;
    const int off = g_offsets[e];
    const int tid = threadIdx.x, lane = tid & 31, wid = tid >> 5;
    const int wm = wid & 3, wn = wid >> 2;
    extern __shared__ char smem[];
    uint32_t sb0 = (uint32_t)__cvta_generic_to_shared(smem);
    const size_t wOff = ((size_t)e * HD + (size_t)nt * 64) * ID;
    const bf16* BH = g_wd_hi + wOff;
    const bf16* BL = g_wd_lo + wOff;

    float acc[2][4][4];
    #pragma unroll
    for (int a = 0; a < 2; a++)
        #pragma unroll
        for (int b = 0; b < 4; b++)
            #pragma unroll
            for (int c = 0; c < 4; c++) acc[a][b][c] = 0.f;

    auto load_stage = [&](int s, int kb) {
        uint32_t sb = sb0 + (uint32_t)s * 49152u;
        int k0 = kb * 64;
        #pragma unroll
        for (int it = 0; it < 4; ++it) {
            int ch = tid + it * 256, r = ch >> 3, c = ch & 7;
            bool v = (mt * 128 + r) < count;
            size_t o = (size_t)(v ? (off + mt * 128 + r) : 0) * ID + (size_t)(k0 + c * 8);
            uint32_t d = sb + r * 128 + ((c ^ (r & 7)) << 4);
            cp16(d,          g_hid_hi + o, v);
            cp16(d + 16384u, g_hid_lo + o, v);
        }
        #pragma unroll
        for (int it = 0; it < 2; ++it) {
            int ch = tid + it * 256, r = ch >> 3, c = ch & 7;
            size_t o = (size_t)r * ID + (size_t)(k0 + c * 8);
            uint32_t d = sb + 32768u + r * 128 + ((c ^ (r & 7)) << 4);
            cp16(d,         BH + o, true);
            cp16(d + 8192u, BL + o, true);
        }
    };

    load_stage(0, 0);
    asm volatile("cp.async.commit_group;\n");
    load_stage(1, 1);
    asm volatile("cp.async.commit_group;\n");

    const int NK = ID / 64;   // 64
    for (int kb = 0; kb < NK; ++kb) {
        if (kb + 1 < NK) asm volatile("cp.async.wait_group 1;\n");
        else             asm volatile("cp.async.wait_group 0;\n");
        __syncthreads();
        int cur = kb % 3;
        uint32_t sb = sb0 + (uint32_t)cur * 49152u;
        #pragma unroll
        for (int q = 0; q < 4; ++q) {
            uint32_t aH[2][4], aL[2][4], bH[2][4], bL[2][4];
            int lr = lane & 15, lc = lane >> 4;
            #pragma unroll
            for (int mi = 0; mi < 2; ++mi) {
                int r = wm * 32 + mi * 16 + lr, c = 2 * q + lc;
                uint32_t ad = sb + r * 128 + ((c ^ (r & 7)) << 4);
                ldsm4(aH[mi], ad);
                ldsm4(aL[mi], ad + 16384u);
            }
            int bn = (lane & 7) + ((lane & 16) >> 1), bc = (lane >> 3) & 1;
            #pragma unroll
            for (int gi = 0; gi < 2; ++gi) {
                int r = wn * 32 + gi * 16 + bn, c = 2 * q + bc;
                uint32_t bd = sb + 32768u + r * 128 + ((c ^ (r & 7)) << 4);
                ldsm4(bH[gi], bd);
                ldsm4(bL[gi], bd + 8192u);
            }
            #pragma unroll
            for (int mi = 0; mi < 2; ++mi)
                #pragma unroll
                for (int nj = 0; nj < 4; ++nj) {
                    int gi = nj >> 1, sub = (nj & 1) * 2;
                    mma16816(acc[mi][nj], aH[mi], &bH[gi][sub]);
                    mma16816(acc[mi][nj], aH[mi], &bL[gi][sub]);
                    mma16816(acc[mi][nj], aL[mi], &bH[gi][sub]);
                }
        }
        if (kb + 2 < NK) {
            load_stage((kb + 2) % 3, kb + 2);
            asm volatile("cp.async.commit_group;\n");
        }
    }

    int rl = lane >> 2, cl = (lane & 3) * 2;
    #pragma unroll
    for (int mi = 0; mi < 2; ++mi)
        #pragma unroll
        for (int nj = 0; nj < 4; ++nj)
            #pragma unroll
            for (int hh = 0; hh < 2; ++hh) {
                int i = mt * 128 + wm * 32 + mi * 16 + hh * 8 + rl;
                if (i < count) {
                    int col = nt * 64 + wn * 32 + nj * 8 + cl;
                    float2 v = make_float2(acc[mi][nj][hh*2], acc[mi][nj][hh*2+1]);
                    *reinterpret_cast<float2*>(&g_contrib[(size_t)(off + i) * HD + col]) = v;
                }
            }
}

// ----------------- combine: out[t] = w0*contrib[r0] + w1*contrib[r1] -----------------
__global__ void combine_kernel(float* __restrict__ out) {
    int i = blockIdx.x * 256 + threadIdx.x;             // over TTOK*HD/4
    if (i >= TTOK * HD / 4) return;
    int t = i / (HD / 4), j = (i % (HD / 4)) * 4;
    int   r0 = g_pair_row[2*t],  r1 = g_pair_row[2*t+1];
    float w0 = g_top_w[2*t],     w1 = g_top_w[2*t+1];
    float4 a = *reinterpret_cast<const float4*>(&g_contrib[(size_t)r0 * HD + j]);
    float4 b = *reinterpret_cast<const float4*>(&g_contrib[(size_t)r1 * HD + j]);
    float4 o;
    o.x = w0*a.x + w1*b.x;  o.y = w0*a.y + w1*b.y;
    o.z = w0*a.z + w1*b.z;  o.w = w0*a.w + w1*b.w;
    reinterpret_cast<float4*>(out)[i] = o;
}

// ----------------- launch -----------------
extern "C" void kernel_launch(void* const* d_in, const int* in_sizes, int n_in,
                              void* d_out, int out_size) {
    const float* x  = (const float*)d_in[0];
    const float* gw = (const float*)d_in[1];
    const float* wg = (const float*)d_in[2];
    const float* wu = (const float*)d_in[3];
    const float* wd = (const float*)d_in[4];
    float* out = (float*)d_out;

    void *xh, *xl, *wgh, *wgl, *wuh, *wul, *wdh, *wdl;
    cudaGetSymbolAddress(&xh,  g_x_hi);  cudaGetSymbolAddress(&xl,  g_x_lo);
    cudaGetSymbolAddress(&wgh, g_wg_hi); cudaGetSymbolAddress(&wgl, g_wg_lo);
    cudaGetSymbolAddress(&wuh, g_wu_hi); cudaGetSymbolAddress(&wul, g_wu_lo);
    cudaGetSymbolAddress(&wdh, g_wd_hi); cudaGetSymbolAddress(&wdl, g_wd_lo);

    cudaFuncSetAttribute(gemm1_kernel, cudaFuncAttributeMaxDynamicSharedMemorySize, 196608);
    cudaFuncSetAttribute(gemm2_kernel, cudaFuncAttributeMaxDynamicSharedMemorySize, 147456);

    init_kernel<<<1, 32>>>();

    int nx = TTOK * HD / 4;
    int nw = (int)((size_t)EN * ID * HD / 4);
    split_kernel<<<(nx + 255) / 256, 256>>>(x,  (bf16*)xh,  (bf16*)xl,  nx);
    split_kernel<<<(nw + 255) / 256, 256>>>(wg, (bf16*)wgh, (bf16*)wgl, nw);
    split_kernel<<<(nw + 255) / 256, 256>>>(wu, (bf16*)wuh, (bf16*)wul, nw);
    split_kernel<<<(nw + 255) / 256, 256>>>(wd, (bf16*)wdh, (bf16*)wdl, nw);

    router_kernel<<<TTOK, 256>>>(x, gw);
    scan_kernel<<<1, 1>>>();
    scatter_kernel<<<(TTOK + 255) / 256, 256>>>();

    dim3 g1(ID / 64, 32, EN);           // nt, mt (max count 4096 -> 32 tiles), expert
    gemm1_kernel<<<g1, 256, 196608>>>();

    dim3 g2(HD / 64, 32, EN);
    gemm2_kernel<<<g2, 256, 147456>>>();

    combine_kernel<<<(TTOK * HD / 4 + 255) / 256, 256>>>(out);
    (void)in_sizes; (void)n_in; (void)out_size;
}

// round 9
// speedup vs baseline: 1.3709x; 1.3709x over previous
#include <cuda_runtime.h>
#include <cuda_fp16.h>
#include <cstdint>

#define TTOK 4096
#define HD   1024
#define EN   8
#define ID   4096
#define RTOT 8192

// ----------------- scratch (device globals; no allocation allowed) -----------------
__device__ __align__(16) __half g_x_hi[(size_t)TTOK * HD];
__device__ __align__(16) __half g_x_lo[(size_t)TTOK * HD];
__device__ __align__(16) __half g_wg[(size_t)EN * ID * HD];
__device__ __align__(16) __half g_wu[(size_t)EN * ID * HD];
__device__ __align__(16) __half g_wd[(size_t)EN * HD * ID];
__device__ __align__(16) __half g_hid_hi[(size_t)RTOT * ID];
__device__ __align__(16) __half g_hid_lo[(size_t)RTOT * ID];
__device__ __align__(16) float  g_contrib[(size_t)RTOT * HD];
__device__ int   g_counts[EN];
__device__ int   g_cursor[EN];
__device__ int   g_offsets[EN + 1];
__device__ float g_top_w[TTOK * 2];
__device__ int   g_top_e[TTOK * 2];
__device__ int   g_token_list[RTOT];
__device__ int   g_pair_row[TTOK * 2];

// ----------------- helpers -----------------
__device__ __forceinline__ void cp16(uint32_t dst, const void* src, bool pred) {
    int sz = pred ? 16 : 0;
    asm volatile("cp.async.cg.shared.global [%0], [%1], 16, %2;\n" :: "r"(dst), "l"(src), "r"(sz));
}
__device__ __forceinline__ void ldsm4(uint32_t* r, uint32_t a) {
    asm volatile("ldmatrix.sync.aligned.m8n8.x4.shared.b16 {%0,%1,%2,%3}, [%4];\n"
                 : "=r"(r[0]), "=r"(r[1]), "=r"(r[2]), "=r"(r[3]) : "r"(a));
}
__device__ __forceinline__ void mma16816(float* d, const uint32_t* a, const uint32_t* b) {
    asm volatile("mma.sync.aligned.m16n8k16.row.col.f32.f16.f16.f32 "
                 "{%0,%1,%2,%3}, {%4,%5,%6,%7}, {%8,%9}, {%0,%1,%2,%3};\n"
                 : "+f"(d[0]), "+f"(d[1]), "+f"(d[2]), "+f"(d[3])
                 : "r"(a[0]), "r"(a[1]), "r"(a[2]), "r"(a[3]), "r"(b[0]), "r"(b[1]));
}

// ----------------- small kernels -----------------
__global__ void init_kernel() {
    int i = threadIdx.x;
    if (i < EN) { g_counts[i] = 0; g_cursor[i] = 0; }
}

// x: fp32 -> fp16 hi + fp16 lo (residual)
__global__ void split_x_kernel(const float* __restrict__ src, int n4) {
    int i = blockIdx.x * 256 + threadIdx.x;
    if (i >= n4) return;
    float4 v = reinterpret_cast<const float4*>(src)[i];
    __half h0 = __float2half(v.x), h1 = __float2half(v.y);
    __half h2 = __float2half(v.z), h3 = __float2half(v.w);
    __half l0 = __float2half(v.x - __half2float(h0));
    __half l1 = __float2half(v.y - __half2float(h1));
    __half l2 = __float2half(v.z - __half2float(h2));
    __half l3 = __float2half(v.w - __half2float(h3));
    reinterpret_cast<__half2*>(g_x_hi)[2*i]   = __halves2half2(h0, h1);
    reinterpret_cast<__half2*>(g_x_hi)[2*i+1] = __halves2half2(h2, h3);
    reinterpret_cast<__half2*>(g_x_lo)[2*i]   = __halves2half2(l0, l1);
    reinterpret_cast<__half2*>(g_x_lo)[2*i+1] = __halves2half2(l2, l3);
}

// weights: fp32 -> fp16
__global__ void cvt_kernel(const float* __restrict__ src, __half* __restrict__ dst, int n4) {
    int i = blockIdx.x * 256 + threadIdx.x;
    if (i >= n4) return;
    float4 v = reinterpret_cast<const float4*>(src)[i];
    reinterpret_cast<__half2*>(dst)[2*i]   = __halves2half2(__float2half(v.x), __float2half(v.y));
    reinterpret_cast<__half2*>(dst)[2*i+1] = __halves2half2(__float2half(v.z), __float2half(v.w));
}

__global__ void router_kernel(const float* __restrict__ x, const float* __restrict__ gw) {
    int t = blockIdx.x;
    int lane = threadIdx.x & 31, w = threadIdx.x >> 5;       // warp w -> expert w
    __shared__ float lg[EN];
    const float* xr = x + (size_t)t * HD;
    const float* g  = gw + (size_t)w * HD;
    float s = 0.f;
    #pragma unroll 8
    for (int j = lane; j < HD; j += 32) s += xr[j] * g[j];
    #pragma unroll
    for (int o = 16; o; o >>= 1) s += __shfl_xor_sync(0xffffffffu, s, o);
    if (lane == 0) lg[w] = s;
    __syncthreads();
    if (threadIdx.x == 0) {
        float v0 = -1e30f; int e0 = 0;
        #pragma unroll
        for (int e = 0; e < EN; e++) if (lg[e] > v0) { v0 = lg[e]; e0 = e; }
        float v1 = -1e30f; int e1 = 0;
        #pragma unroll
        for (int e = 0; e < EN; e++) if (e != e0 && lg[e] > v1) { v1 = lg[e]; e1 = e; }
        float b = __expf(v1 - v0);
        g_top_e[2*t] = e0;  g_top_e[2*t+1] = e1;
        g_top_w[2*t] = 1.f / (1.f + b);  g_top_w[2*t+1] = b / (1.f + b);
        atomicAdd(&g_counts[e0], 1);
        atomicAdd(&g_counts[e1], 1);
    }
}

__global__ void scan_kernel() {
    if (threadIdx.x == 0) {
        int o = 0;
        for (int e = 0; e < EN; e++) { g_offsets[e] = o; o += g_counts[e]; }
        g_offsets[EN] = o;
    }
}

__global__ void scatter_kernel() {
    int t = blockIdx.x * 256 + threadIdx.x;
    if (t >= TTOK) return;
    #pragma unroll
    for (int k = 0; k < 2; k++) {
        int e = g_top_e[2*t+k];
        int r = g_offsets[e] + atomicAdd(&g_cursor[e], 1);
        g_token_list[r] = t;
        g_pair_row[2*t+k] = r;
    }
}

// ===================== GEMM1: (xh+xl) x {wg,wu} fp16 + SwiGLU -> split-fp16 hidden =====================
// Tile 128(M) x 64(N of I), BK=64, 3 stages.
// Stage (48 KB): xh 16K | xl 16K | wg 8K | wu 8K.
#define G1_STAGE 49152u
__global__ __launch_bounds__(256) void gemm1_kernel() {
    const int e = blockIdx.z, mt = blockIdx.y, nt = blockIdx.x;
    const int count = g_counts[e];
    if (mt * 128 >= count) return;
    const int off = g_offsets[e];
    const int tid = threadIdx.x, lane = tid & 31, wid = tid >> 5;
    const int wm = wid & 3, wn = wid >> 2;                   // 4x2 warps -> 32x32 each
    extern __shared__ char smem[];
    __shared__ int rows_s[128];
    if (tid < 128) {
        int i = mt * 128 + tid;
        rows_s[tid] = (i < count) ? g_token_list[off + i] : -1;
    }
    __syncthreads();
    uint32_t sb0 = (uint32_t)__cvta_generic_to_shared(smem);
    const size_t wOff = ((size_t)e * ID + (size_t)nt * 64) * HD;
    const __half* Bg = g_wg + wOff;
    const __half* Bu = g_wu + wOff;

    float ag[2][4][4], au[2][4][4];
    #pragma unroll
    for (int a = 0; a < 2; a++)
        #pragma unroll
        for (int b = 0; b < 4; b++)
            #pragma unroll
            for (int c = 0; c < 4; c++) { ag[a][b][c] = 0.f; au[a][b][c] = 0.f; }

    auto load_stage = [&](int s, int kb) {
        uint32_t sb = sb0 + (uint32_t)s * G1_STAGE;
        int k0 = kb * 64;
        #pragma unroll
        for (int it = 0; it < 4; ++it) {                     // A: 128 rows x 8 x 16B (hi+lo)
            int ch = tid + it * 256, r = ch >> 3, c = ch & 7;
            int row = rows_s[r]; bool v = row >= 0;
            size_t o = (size_t)(v ? row : 0) * HD + (size_t)(k0 + c * 8);
            uint32_t d = sb + r * 128 + ((c ^ (r & 7)) << 4);
            cp16(d,          g_x_hi + o, v);
            cp16(d + 16384u, g_x_lo + o, v);
        }
        #pragma unroll
        for (int it = 0; it < 2; ++it) {                     // B: 64 rows x 8 x 16B (x2 mats)
            int ch = tid + it * 256, r = ch >> 3, c = ch & 7;
            size_t o = (size_t)r * HD + (size_t)(k0 + c * 8);
            uint32_t d = sb + 32768u + r * 128 + ((c ^ (r & 7)) << 4);
            cp16(d,         Bg + o, true);
            cp16(d + 8192u, Bu + o, true);
        }
    };

    load_stage(0, 0);
    asm volatile("cp.async.commit_group;\n");
    load_stage(1, 1);
    asm volatile("cp.async.commit_group;\n");

    const int NK = HD / 64;   // 16
    for (int kb = 0; kb < NK; ++kb) {
        if (kb + 1 < NK) asm volatile("cp.async.wait_group 1;\n");
        else             asm volatile("cp.async.wait_group 0;\n");
        __syncthreads();
        int cur = kb % 3;
        uint32_t sb = sb0 + (uint32_t)cur * G1_STAGE;
        #pragma unroll
        for (int q = 0; q < 4; ++q) {
            uint32_t aH[2][4], aL[2][4], bg[2][4], bu[2][4];
            int lr = lane & 15, lc = lane >> 4;
            #pragma unroll
            for (int mi = 0; mi < 2; ++mi) {
                int r = wm * 32 + mi * 16 + lr, c = 2 * q + lc;
                uint32_t ad = sb + r * 128 + ((c ^ (r & 7)) << 4);
                ldsm4(aH[mi], ad);
                ldsm4(aL[mi], ad + 16384u);
            }
            int bn = (lane & 7) + ((lane & 16) >> 1), bc = (lane >> 3) & 1;
            #pragma unroll
            for (int gi = 0; gi < 2; ++gi) {
                int r = wn * 32 + gi * 16 + bn, c = 2 * q + bc;
                uint32_t bd = sb + 32768u + r * 128 + ((c ^ (r & 7)) << 4);
                ldsm4(bg[gi], bd);
                ldsm4(bu[gi], bd + 8192u);
            }
            #pragma unroll
            for (int mi = 0; mi < 2; ++mi)
                #pragma unroll
                for (int nj = 0; nj < 4; ++nj) {
                    int gi = nj >> 1, sub = (nj & 1) * 2;
                    mma16816(ag[mi][nj], aH[mi], &bg[gi][sub]);
                    mma16816(ag[mi][nj], aL[mi], &bg[gi][sub]);
                    mma16816(au[mi][nj], aH[mi], &bu[gi][sub]);
                    mma16816(au[mi][nj], aL[mi], &bu[gi][sub]);
                }
        }
        if (kb + 2 < NK) {
            load_stage((kb + 2) % 3, kb + 2);
            asm volatile("cp.async.commit_group;\n");
        }
    }

    // SwiGLU epilogue -> split-fp16 hidden (h = h_hi + h_lo, exact to ~2^-22)
    int rl = lane >> 2, cl = (lane & 3) * 2;
    #pragma unroll
    for (int mi = 0; mi < 2; ++mi)
        #pragma unroll
        for (int nj = 0; nj < 4; ++nj)
            #pragma unroll
            for (int hh = 0; hh < 2; ++hh) {
                int i = mt * 128 + wm * 32 + mi * 16 + hh * 8 + rl;
                if (i < count) {
                    int col = nt * 64 + wn * 32 + nj * 8 + cl;
                    float g0 = ag[mi][nj][hh*2], g1 = ag[mi][nj][hh*2+1];
                    float u0 = au[mi][nj][hh*2], u1 = au[mi][nj][hh*2+1];
                    float h0 = g0 * (1.f / (1.f + __expf(-g0))) * u0;
                    float h1 = g1 * (1.f / (1.f + __expf(-g1))) * u1;
                    __half a0 = __float2half(h0), a1 = __float2half(h1);
                    __half b0 = __float2half(h0 - __half2float(a0));
                    __half b1 = __float2half(h1 - __half2float(a1));
                    size_t idx = (size_t)(off + i) * ID + col;
                    *reinterpret_cast<__half2*>(g_hid_hi + idx) = __halves2half2(a0, a1);
                    *reinterpret_cast<__half2*>(g_hid_lo + idx) = __halves2half2(b0, b1);
                }
            }
}

// ===================== GEMM2: (hid_hi+hid_lo) x wd(fp16) -> contrib =====================
// Tile 128(M) x 64(N of H), BK=64 over I, 4 stages. Stage (40 KB): Ah 16K | Al 16K | B 8K.
#define G2_STAGE 40960u
__global__ __launch_bounds__(256) void gemm2_kernel() {
    const int e = blockIdx.z, mt = blockIdx.y, nt = blockIdx.x;
    const int count = g_counts[e];
    if (mt * 128 >= count) return;
    const int off = g_offsets[e];
    const int tid = threadIdx.x, lane = tid & 31, wid = tid >> 5;
    const int wm = wid & 3, wn = wid >> 2;
    extern __shared__ char smem[];
    uint32_t sb0 = (uint32_t)__cvta_generic_to_shared(smem);
    const size_t wOff = ((size_t)e * HD + (size_t)nt * 64) * ID;
    const __half* BW = g_wd + wOff;

    float acc[2][4][4];
    #pragma unroll
    for (int a = 0; a < 2; a++)
        #pragma unroll
        for (int b = 0; b < 4; b++)
            #pragma unroll
            for (int c = 0; c < 4; c++) acc[a][b][c] = 0.f;

    auto load_stage = [&](int s, int kb) {
        uint32_t sb = sb0 + (uint32_t)s * G2_STAGE;
        int k0 = kb * 64;
        #pragma unroll
        for (int it = 0; it < 4; ++it) {                     // A: 128 rows x 8 x 16B (hi+lo)
            int ch = tid + it * 256, r = ch >> 3, c = ch & 7;
            bool v = (mt * 128 + r) < count;
            size_t o = (size_t)(v ? (off + mt * 128 + r) : 0) * ID + (size_t)(k0 + c * 8);
            uint32_t d = sb + r * 128 + ((c ^ (r & 7)) << 4);
            cp16(d,          g_hid_hi + o, v);
            cp16(d + 16384u, g_hid_lo + o, v);
        }
        #pragma unroll
        for (int it = 0; it < 2; ++it) {                     // B: 64 rows x 8 x 16B
            int ch = tid + it * 256, r = ch >> 3, c = ch & 7;
            size_t o = (size_t)r * ID + (size_t)(k0 + c * 8);
            uint32_t d = sb + 32768u + r * 128 + ((c ^ (r & 7)) << 4);
            cp16(d, BW + o, true);
        }
    };

    load_stage(0, 0);
    asm volatile("cp.async.commit_group;\n");
    load_stage(1, 1);
    asm volatile("cp.async.commit_group;\n");
    load_stage(2, 2);
    asm volatile("cp.async.commit_group;\n");

    const int NK = ID / 64;   // 64
    for (int kb = 0; kb < NK; ++kb) {
        if (kb + 2 < NK)      asm volatile("cp.async.wait_group 2;\n");
        else if (kb + 1 < NK) asm volatile("cp.async.wait_group 1;\n");
        else                  asm volatile("cp.async.wait_group 0;\n");
        __syncthreads();
        int cur = kb & 3;
        uint32_t sb = sb0 + (uint32_t)cur * G2_STAGE;
        #pragma unroll
        for (int q = 0; q < 4; ++q) {
            uint32_t aH[2][4], aL[2][4], bF[2][4];
            int lr = lane & 15, lc = lane >> 4;
            #pragma unroll
            for (int mi = 0; mi < 2; ++mi) {
                int r = wm * 32 + mi * 16 + lr, c = 2 * q + lc;
                uint32_t ad = sb + r * 128 + ((c ^ (r & 7)) << 4);
                ldsm4(aH[mi], ad);
                ldsm4(aL[mi], ad + 16384u);
            }
            int bn = (lane & 7) + ((lane & 16) >> 1), bc = (lane >> 3) & 1;
            #pragma unroll
            for (int gi = 0; gi < 2; ++gi) {
                int r = wn * 32 + gi * 16 + bn, c = 2 * q + bc;
                ldsm4(bF[gi], sb + 32768u + r * 128 + ((c ^ (r & 7)) << 4));
            }
            #pragma unroll
            for (int mi = 0; mi < 2; ++mi)
                #pragma unroll
                for (int nj = 0; nj < 4; ++nj) {
                    int gi = nj >> 1, sub = (nj & 1) * 2;
                    mma16816(acc[mi][nj], aH[mi], &bF[gi][sub]);
                    mma16816(acc[mi][nj], aL[mi], &bF[gi][sub]);
                }
        }
        if (kb + 3 < NK) {
            load_stage((kb + 3) & 3, kb + 3);
            asm volatile("cp.async.commit_group;\n");
        }
    }

    int rl = lane >> 2, cl = (lane & 3) * 2;
    #pragma unroll
    for (int mi = 0; mi < 2; ++mi)
        #pragma unroll
        for (int nj = 0; nj < 4; ++nj)
            #pragma unroll
            for (int hh = 0; hh < 2; ++hh) {
                int i = mt * 128 + wm * 32 + mi * 16 + hh * 8 + rl;
                if (i < count) {
                    int col = nt * 64 + wn * 32 + nj * 8 + cl;
                    float2 v = make_float2(acc[mi][nj][hh*2], acc[mi][nj][hh*2+1]);
                    *reinterpret_cast<float2*>(&g_contrib[(size_t)(off + i) * HD + col]) = v;
                }
            }
}

// ----------------- combine: out[t] = w0*contrib[r0] + w1*contrib[r1] -----------------
__global__ void combine_kernel(float* __restrict__ out) {
    int i = blockIdx.x * 256 + threadIdx.x;             // over TTOK*HD/4
    if (i >= TTOK * HD / 4) return;
    int t = i / (HD / 4), j = (i % (HD / 4)) * 4;
    int   r0 = g_pair_row[2*t],  r1 = g_pair_row[2*t+1];
    float w0 = g_top_w[2*t],     w1 = g_top_w[2*t+1];
    float4 a = *reinterpret_cast<const float4*>(&g_contrib[(size_t)r0 * HD + j]);
    float4 b = *reinterpret_cast<const float4*>(&g_contrib[(size_t)r1 * HD + j]);
    float4 o;
    o.x = w0*a.x + w1*b.x;  o.y = w0*a.y + w1*b.y;
    o.z = w0*a.z + w1*b.z;  o.w = w0*a.w + w1*b.w;
    reinterpret_cast<float4*>(out)[i] = o;
}

// ----------------- launch -----------------
extern "C" void kernel_launch(void* const* d_in, const int* in_sizes, int n_in,
                              void* d_out, int out_size) {
    const float* x  = (const float*)d_in[0];
    const float* gw = (const float*)d_in[1];
    const float* wg = (const float*)d_in[2];
    const float* wu = (const float*)d_in[3];
    const float* wd = (const float*)d_in[4];
    float* out = (float*)d_out;

    void *wgp, *wup, *wdp;
    cudaGetSymbolAddress(&wgp, g_wg);
    cudaGetSymbolAddress(&wup, g_wu);
    cudaGetSymbolAddress(&wdp, g_wd);

    const int g1_smem = 3 * (int)G1_STAGE;   // 147456
    const int g2_smem = 4 * (int)G2_STAGE;   // 163840
    cudaFuncSetAttribute(gemm1_kernel, cudaFuncAttributeMaxDynamicSharedMemorySize, g1_smem);
    cudaFuncSetAttribute(gemm2_kernel, cudaFuncAttributeMaxDynamicSharedMemorySize, g2_smem);

    init_kernel<<<1, 32>>>();

    int nx = TTOK * HD / 4;
    int nw = (int)((size_t)EN * ID * HD / 4);
    split_x_kernel<<<(nx + 255) / 256, 256>>>(x, nx);
    cvt_kernel<<<(nw + 255) / 256, 256>>>(wg, (__half*)wgp, nw);
    cvt_kernel<<<(nw + 255) / 256, 256>>>(wu, (__half*)wup, nw);
    cvt_kernel<<<(nw + 255) / 256, 256>>>(wd, (__half*)wdp, nw);

    router_kernel<<<TTOK, 256>>>(x, gw);
    scan_kernel<<<1, 1>>>();
    scatter_kernel<<<(TTOK + 255) / 256, 256>>>();

    dim3 g1(ID / 64, 32, EN);           // nt, mt (max count 4096 -> 32 tiles), expert
    gemm1_kernel<<<g1, 256, g1_smem>>>();

    dim3 g2(HD / 64, 32, EN);
    gemm2_kernel<<<g2, 256, g2_smem>>>();

    combine_kernel<<<(TTOK * HD / 4 + 255) / 256, 256>>>(out);
    (void)in_sizes; (void)n_in; (void)out_size;
}

// round 16
// speedup vs baseline: 2.1419x; 1.5624x over previous
#include <cuda_runtime.h>
#include <cuda_fp16.h>
#include <cstdint>

#define TTOK 4096
#define HD   1024
#define EN   8
#define ID   4096
#define RTOT 8192

// ----------------- scratch (device globals; no allocation allowed) -----------------
__device__ __align__(16) __half g_x16[(size_t)TTOK * HD];
__device__ __align__(16) __half g_wg[(size_t)EN * ID * HD];
__device__ __align__(16) __half g_wu[(size_t)EN * ID * HD];
__device__ __align__(16) __half g_wd[(size_t)EN * HD * ID];
__device__ __align__(16) __half g_hid[(size_t)RTOT * ID];
__device__ __align__(16) float  g_contrib[(size_t)RTOT * HD];
__device__ int   g_counts[EN];
__device__ int   g_cursor[EN];
__device__ int   g_offsets[EN + 1];
__device__ float g_top_w[TTOK * 2];
__device__ int   g_top_e[TTOK * 2];
__device__ int   g_token_list[RTOT];
__device__ int   g_pair_row[TTOK * 2];

// ----------------- helpers -----------------
__device__ __forceinline__ void cp16(uint32_t dst, const void* src, bool pred) {
    int sz = pred ? 16 : 0;
    asm volatile("cp.async.cg.shared.global [%0], [%1], 16, %2;\n" :: "r"(dst), "l"(src), "r"(sz));
}
__device__ __forceinline__ void ldsm4(uint32_t* r, uint32_t a) {
    asm volatile("ldmatrix.sync.aligned.m8n8.x4.shared.b16 {%0,%1,%2,%3}, [%4];\n"
                 : "=r"(r[0]), "=r"(r[1]), "=r"(r[2]), "=r"(r[3]) : "r"(a));
}
__device__ __forceinline__ void mma16816(float* d, const uint32_t* a, const uint32_t* b) {
    asm volatile("mma.sync.aligned.m16n8k16.row.col.f32.f16.f16.f32 "
                 "{%0,%1,%2,%3}, {%4,%5,%6,%7}, {%8,%9}, {%0,%1,%2,%3};\n"
                 : "+f"(d[0]), "+f"(d[1]), "+f"(d[2]), "+f"(d[3])
                 : "r"(a[0]), "r"(a[1]), "r"(a[2]), "r"(a[3]), "r"(b[0]), "r"(b[1]));
}

// ----------------- small kernels -----------------
__global__ void init_kernel() {
    int i = threadIdx.x;
    if (i < EN) { g_counts[i] = 0; g_cursor[i] = 0; }
}

// fp32 -> fp16
__global__ void cvt_kernel(const float* __restrict__ src, __half* __restrict__ dst, int n4) {
    int i = blockIdx.x * 256 + threadIdx.x;
    if (i >= n4) return;
    float4 v = reinterpret_cast<const float4*>(src)[i];
    reinterpret_cast<__half2*>(dst)[2*i]   = __halves2half2(__float2half(v.x), __float2half(v.y));
    reinterpret_cast<__half2*>(dst)[2*i+1] = __halves2half2(__float2half(v.z), __float2half(v.w));
}

__global__ void router_kernel(const float* __restrict__ x, const float* __restrict__ gw) {
    int t = blockIdx.x;
    int lane = threadIdx.x & 31, w = threadIdx.x >> 5;       // warp w -> expert w
    __shared__ float lg[EN];
    const float* xr = x + (size_t)t * HD;
    const float* g  = gw + (size_t)w * HD;
    float s = 0.f;
    #pragma unroll 8
    for (int j = lane; j < HD; j += 32) s += xr[j] * g[j];
    #pragma unroll
    for (int o = 16; o; o >>= 1) s += __shfl_xor_sync(0xffffffffu, s, o);
    if (lane == 0) lg[w] = s;
    __syncthreads();
    if (threadIdx.x == 0) {
        float v0 = -1e30f; int e0 = 0;
        #pragma unroll
        for (int e = 0; e < EN; e++) if (lg[e] > v0) { v0 = lg[e]; e0 = e; }
        float v1 = -1e30f; int e1 = 0;
        #pragma unroll
        for (int e = 0; e < EN; e++) if (e != e0 && lg[e] > v1) { v1 = lg[e]; e1 = e; }
        float b = __expf(v1 - v0);
        g_top_e[2*t] = e0;  g_top_e[2*t+1] = e1;
        g_top_w[2*t] = 1.f / (1.f + b);  g_top_w[2*t+1] = b / (1.f + b);
        atomicAdd(&g_counts[e0], 1);
        atomicAdd(&g_counts[e1], 1);
    }
}

__global__ void scan_kernel() {
    if (threadIdx.x == 0) {
        int o = 0;
        for (int e = 0; e < EN; e++) { g_offsets[e] = o; o += g_counts[e]; }
        g_offsets[EN] = o;
    }
}

__global__ void scatter_kernel() {
    int t = blockIdx.x * 256 + threadIdx.x;
    if (t >= TTOK) return;
    #pragma unroll
    for (int k = 0; k < 2; k++) {
        int e = g_top_e[2*t+k];
        int r = g_offsets[e] + atomicAdd(&g_cursor[e], 1);
        g_token_list[r] = t;
        g_pair_row[2*t+k] = r;
    }
}

// ===================== GEMM1: x(fp16) x {wg,wu}(fp16) + SwiGLU -> fp16 hidden =====================
// Tile 128(M) x 64(N of I), BK=64, 4 stages. Stage (32 KB): x 16K | wg 8K | wu 8K.
#define G1_STAGE 32768u
__global__ __launch_bounds__(256) void gemm1_kernel() {
    const int e = blockIdx.z, mt = blockIdx.y, nt = blockIdx.x;
    const int count = g_counts[e];
    if (mt * 128 >= count) return;
    const int off = g_offsets[e];
    const int tid = threadIdx.x, lane = tid & 31, wid = tid >> 5;
    const int wm = wid & 3, wn = wid >> 2;                   // 4x2 warps -> 32x32 each
    extern __shared__ char smem[];
    __shared__ int rows_s[128];
    if (tid < 128) {
        int i = mt * 128 + tid;
        rows_s[tid] = (i < count) ? g_token_list[off + i] : -1;
    }
    __syncthreads();
    uint32_t sb0 = (uint32_t)__cvta_generic_to_shared(smem);
    const size_t wOff = ((size_t)e * ID + (size_t)nt * 64) * HD;
    const __half* Bg = g_wg + wOff;
    const __half* Bu = g_wu + wOff;

    float ag[2][4][4], au[2][4][4];
    #pragma unroll
    for (int a = 0; a < 2; a++)
        #pragma unroll
        for (int b = 0; b < 4; b++)
            #pragma unroll
            for (int c = 0; c < 4; c++) { ag[a][b][c] = 0.f; au[a][b][c] = 0.f; }

    auto load_stage = [&](int s, int kb) {
        uint32_t sb = sb0 + (uint32_t)s * G1_STAGE;
        int k0 = kb * 64;
        #pragma unroll
        for (int it = 0; it < 4; ++it) {                     // A: 128 rows x 8 x 16B
            int ch = tid + it * 256, r = ch >> 3, c = ch & 7;
            int row = rows_s[r]; bool v = row >= 0;
            size_t o = (size_t)(v ? row : 0) * HD + (size_t)(k0 + c * 8);
            uint32_t d = sb + r * 128 + ((c ^ (r & 7)) << 4);
            cp16(d, g_x16 + o, v);
        }
        #pragma unroll
        for (int it = 0; it < 2; ++it) {                     // B: 64 rows x 8 x 16B (x2 mats)
            int ch = tid + it * 256, r = ch >> 3, c = ch & 7;
            size_t o = (size_t)r * HD + (size_t)(k0 + c * 8);
            uint32_t d = sb + 16384u + r * 128 + ((c ^ (r & 7)) << 4);
            cp16(d,         Bg + o, true);
            cp16(d + 8192u, Bu + o, true);
        }
    };

    load_stage(0, 0);
    asm volatile("cp.async.commit_group;\n");
    load_stage(1, 1);
    asm volatile("cp.async.commit_group;\n");
    load_stage(2, 2);
    asm volatile("cp.async.commit_group;\n");

    const int NK = HD / 64;   // 16
    for (int kb = 0; kb < NK; ++kb) {
        if (kb + 2 < NK)      asm volatile("cp.async.wait_group 2;\n");
        else if (kb + 1 < NK) asm volatile("cp.async.wait_group 1;\n");
        else                  asm volatile("cp.async.wait_group 0;\n");
        __syncthreads();
        int cur = kb & 3;
        uint32_t sb = sb0 + (uint32_t)cur * G1_STAGE;
        #pragma unroll
        for (int q = 0; q < 4; ++q) {
            uint32_t aF[2][4], bg[2][4], bu[2][4];
            int lr = lane & 15, lc = lane >> 4;
            #pragma unroll
            for (int mi = 0; mi < 2; ++mi) {
                int r = wm * 32 + mi * 16 + lr, c = 2 * q + lc;
                ldsm4(aF[mi], sb + r * 128 + ((c ^ (r & 7)) << 4));
            }
            int bn = (lane & 7) + ((lane & 16) >> 1), bc = (lane >> 3) & 1;
            #pragma unroll
            for (int gi = 0; gi < 2; ++gi) {
                int r = wn * 32 + gi * 16 + bn, c = 2 * q + bc;
                uint32_t bd = sb + 16384u + r * 128 + ((c ^ (r & 7)) << 4);
                ldsm4(bg[gi], bd);
                ldsm4(bu[gi], bd + 8192u);
            }
            #pragma unroll
            for (int mi = 0; mi < 2; ++mi)
                #pragma unroll
                for (int nj = 0; nj < 4; ++nj) {
                    int gi = nj >> 1, sub = (nj & 1) * 2;
                    mma16816(ag[mi][nj], aF[mi], &bg[gi][sub]);
                    mma16816(au[mi][nj], aF[mi], &bu[gi][sub]);
                }
        }
        if (kb + 3 < NK) {
            load_stage((kb + 3) & 3, kb + 3);
            asm volatile("cp.async.commit_group;\n");
        }
    }

    // SwiGLU epilogue -> fp16 hidden
    int rl = lane >> 2, cl = (lane & 3) * 2;
    #pragma unroll
    for (int mi = 0; mi < 2; ++mi)
        #pragma unroll
        for (int nj = 0; nj < 4; ++nj)
            #pragma unroll
            for (int hh = 0; hh < 2; ++hh) {
                int i = mt * 128 + wm * 32 + mi * 16 + hh * 8 + rl;
                if (i < count) {
                    int col = nt * 64 + wn * 32 + nj * 8 + cl;
                    float g0 = ag[mi][nj][hh*2], g1 = ag[mi][nj][hh*2+1];
                    float u0 = au[mi][nj][hh*2], u1 = au[mi][nj][hh*2+1];
                    float h0 = g0 * (1.f / (1.f + __expf(-g0))) * u0;
                    float h1 = g1 * (1.f / (1.f + __expf(-g1))) * u1;
                    size_t idx = (size_t)(off + i) * ID + col;
                    *reinterpret_cast<__half2*>(g_hid + idx) =
                        __halves2half2(__float2half(h0), __float2half(h1));
                }
            }
}

// ===================== GEMM2: hidden(fp16) x wd(fp16) -> contrib =====================
// Tile 128(M) x 64(N of H), BK=64 over I, 4 stages. Stage (24 KB): A 16K | B 8K.
#define G2_STAGE 24576u
__global__ __launch_bounds__(256) void gemm2_kernel() {
    const int e = blockIdx.z, mt = blockIdx.y, nt = blockIdx.x;
    const int count = g_counts[e];
    if (mt * 128 >= count) return;
    const int off = g_offsets[e];
    const int tid = threadIdx.x, lane = tid & 31, wid = tid >> 5;
    const int wm = wid & 3, wn = wid >> 2;
    extern __shared__ char smem[];
    uint32_t sb0 = (uint32_t)__cvta_generic_to_shared(smem);
    const size_t wOff = ((size_t)e * HD + (size_t)nt * 64) * ID;
    const __half* BW = g_wd + wOff;

    float acc[2][4][4];
    #pragma unroll
    for (int a = 0; a < 2; a++)
        #pragma unroll
        for (int b = 0; b < 4; b++)
            #pragma unroll
            for (int c = 0; c < 4; c++) acc[a][b][c] = 0.f;

    auto load_stage = [&](int s, int kb) {
        uint32_t sb = sb0 + (uint32_t)s * G2_STAGE;
        int k0 = kb * 64;
        #pragma unroll
        for (int it = 0; it < 4; ++it) {                     // A: 128 rows x 8 x 16B
            int ch = tid + it * 256, r = ch >> 3, c = ch & 7;
            bool v = (mt * 128 + r) < count;
            size_t o = (size_t)(v ? (off + mt * 128 + r) : 0) * ID + (size_t)(k0 + c * 8);
            uint32_t d = sb + r * 128 + ((c ^ (r & 7)) << 4);
            cp16(d, g_hid + o, v);
        }
        #pragma unroll
        for (int it = 0; it < 2; ++it) {                     // B: 64 rows x 8 x 16B
            int ch = tid + it * 256, r = ch >> 3, c = ch & 7;
            size_t o = (size_t)r * ID + (size_t)(k0 + c * 8);
            uint32_t d = sb + 16384u + r * 128 + ((c ^ (r & 7)) << 4);
            cp16(d, BW + o, true);
        }
    };

    load_stage(0, 0);
    asm volatile("cp.async.commit_group;\n");
    load_stage(1, 1);
    asm volatile("cp.async.commit_group;\n");
    load_stage(2, 2);
    asm volatile("cp.async.commit_group;\n");

    const int NK = ID / 64;   // 64
    for (int kb = 0; kb < NK; ++kb) {
        if (kb + 2 < NK)      asm volatile("cp.async.wait_group 2;\n");
        else if (kb + 1 < NK) asm volatile("cp.async.wait_group 1;\n");
        else                  asm volatile("cp.async.wait_group 0;\n");
        __syncthreads();
        int cur = kb & 3;
        uint32_t sb = sb0 + (uint32_t)cur * G2_STAGE;
        #pragma unroll
        for (int q = 0; q < 4; ++q) {
            uint32_t aF[2][4], bF[2][4];
            int lr = lane & 15, lc = lane >> 4;
            #pragma unroll
            for (int mi = 0; mi < 2; ++mi) {
                int r = wm * 32 + mi * 16 + lr, c = 2 * q + lc;
                ldsm4(aF[mi], sb + r * 128 + ((c ^ (r & 7)) << 4));
            }
            int bn = (lane & 7) + ((lane & 16) >> 1), bc = (lane >> 3) & 1;
            #pragma unroll
            for (int gi = 0; gi < 2; ++gi) {
                int r = wn * 32 + gi * 16 + bn, c = 2 * q + bc;
                ldsm4(bF[gi], sb + 16384u + r * 128 + ((c ^ (r & 7)) << 4));
            }
            #pragma unroll
            for (int mi = 0; mi < 2; ++mi)
                #pragma unroll
                for (int nj = 0; nj < 4; ++nj) {
                    int gi = nj >> 1, sub = (nj & 1) * 2;
                    mma16816(acc[mi][nj], aF[mi], &bF[gi][sub]);
                }
        }
        if (kb + 3 < NK) {
            load_stage((kb + 3) & 3, kb + 3);
            asm volatile("cp.async.commit_group;\n");
        }
    }

    int rl = lane >> 2, cl = (lane & 3) * 2;
    #pragma unroll
    for (int mi = 0; mi < 2; ++mi)
        #pragma unroll
        for (int nj = 0; nj < 4; ++nj)
            #pragma unroll
            for (int hh = 0; hh < 2; ++hh) {
                int i = mt * 128 + wm * 32 + mi * 16 + hh * 8 + rl;
                if (i < count) {
                    int col = nt * 64 + wn * 32 + nj * 8 + cl;
                    float2 v = make_float2(acc[mi][nj][hh*2], acc[mi][nj][hh*2+1]);
                    *reinterpret_cast<float2*>(&g_contrib[(size_t)(off + i) * HD + col]) = v;
                }
            }
}

// ----------------- combine: out[t] = w0*contrib[r0] + w1*contrib[r1] -----------------
__global__ void combine_kernel(float* __restrict__ out) {
    int i = blockIdx.x * 256 + threadIdx.x;             // over TTOK*HD/4
    if (i >= TTOK * HD / 4) return;
    int t = i / (HD / 4), j = (i % (HD / 4)) * 4;
    int   r0 = g_pair_row[2*t],  r1 = g_pair_row[2*t+1];
    float w0 = g_top_w[2*t],     w1 = g_top_w[2*t+1];
    float4 a = *reinterpret_cast<const float4*>(&g_contrib[(size_t)r0 * HD + j]);
    float4 b = *reinterpret_cast<const float4*>(&g_contrib[(size_t)r1 * HD + j]);
    float4 o;
    o.x = w0*a.x + w1*b.x;  o.y = w0*a.y + w1*b.y;
    o.z = w0*a.z + w1*b.z;  o.w = w0*a.w + w1*b.w;
    reinterpret_cast<float4*>(out)[i] = o;
}

// ----------------- launch -----------------
extern "C" void kernel_launch(void* const* d_in, const int* in_sizes, int n_in,
                              void* d_out, int out_size) {
    const float* x  = (const float*)d_in[0];
    const float* gw = (const float*)d_in[1];
    const float* wg = (const float*)d_in[2];
    const float* wu = (const float*)d_in[3];
    const float* wd = (const float*)d_in[4];
    float* out = (float*)d_out;

    void *xp, *wgp, *wup, *wdp;
    cudaGetSymbolAddress(&xp,  g_x16);
    cudaGetSymbolAddress(&wgp, g_wg);
    cudaGetSymbolAddress(&wup, g_wu);
    cudaGetSymbolAddress(&wdp, g_wd);

    const int g1_smem = 4 * (int)G1_STAGE;   // 131072
    const int g2_smem = 4 * (int)G2_STAGE;   // 98304
    cudaFuncSetAttribute(gemm1_kernel, cudaFuncAttributeMaxDynamicSharedMemorySize, g1_smem);
    cudaFuncSetAttribute(gemm2_kernel, cudaFuncAttributeMaxDynamicSharedMemorySize, g2_smem);

    init_kernel<<<1, 32>>>();

    int nx = TTOK * HD / 4;
    int nw = (int)((size_t)EN * ID * HD / 4);
    cvt_kernel<<<(nx + 255) / 256, 256>>>(x,  (__half*)xp,  nx);
    cvt_kernel<<<(nw + 255) / 256, 256>>>(wg, (__half*)wgp, nw);
    cvt_kernel<<<(nw + 255) / 256, 256>>>(wu, (__half*)wup, nw);
    cvt_kernel<<<(nw + 255) / 256, 256>>>(wd, (__half*)wdp, nw);

    router_kernel<<<TTOK, 256>>>(x, gw);
    scan_kernel<<<1, 1>>>();
    scatter_kernel<<<(TTOK + 255) / 256, 256>>>();

    dim3 g1(ID / 64, 32, EN);           // nt, mt (max count 4096 -> 32 tiles), expert
    gemm1_kernel<<<g1, 256, g1_smem>>>();

    dim3 g2(HD / 64, 32, EN);
    gemm2_kernel<<<g2, 256, g2_smem>>>();

    combine_kernel<<<(TTOK * HD / 4 + 255) / 256, 256>>>(out);
    (void)in_sizes; (void)n_in; (void)out_size;
}